// round 17
// baseline (speedup 1.0000x reference)
#include <cuda_runtime.h>
#include <cuda_bf16.h>
#include <cuda_fp16.h>
#include <cstdint>
#include <math.h>

#define SEQL 2048
#define HID  2048
#define NH   32
#define NKV  8
#define HD   64
#define QKVN 3072
#define GK   2048

// ---------------------------------------------------------------------------
// Scratch (device globals; no allocations allowed)
// ---------------------------------------------------------------------------
__device__ __half g_hid[SEQL * HID];            // hidden single fp16
__device__ __half g_wqkvT[QKVN * GK];           // weights single fp16, transposed
__device__ __half g_woT[HID * GK];
__device__ __half g_attn[SEQL * HID];           // attention out single fp16
__device__ __half g_q1[SEQL * NH * HD];         // q single fp16 (x0.125, rope'd)
__device__ __half g_k1[SEQL * NKV * HD];        // k single fp16 (rope'd)
__device__ __half g_v1[SEQL * NKV * HD];        // v single fp16
__device__ float2 g_rope[SEQL * 32];            // (cos, sin) per (s, j)

// ---------------------------------------------------------------------------
// PTX helpers (baseline sm_80+ only)
// ---------------------------------------------------------------------------
__device__ __forceinline__ uint32_t smem_u32(const void* p) {
    uint32_t a;
    asm("{ .reg .u64 t; cvta.to.shared.u64 t, %1; cvt.u32.u64 %0, t; }" : "=r"(a) : "l"(p));
    return a;
}
#define LDMX4(r, addr) \
    asm volatile("ldmatrix.sync.aligned.m8n8.x4.shared.b16 {%0,%1,%2,%3}, [%4];" \
        : "=r"((r)[0]), "=r"((r)[1]), "=r"((r)[2]), "=r"((r)[3]) : "r"(addr))
#define LDMX4T(r, addr) \
    asm volatile("ldmatrix.sync.aligned.m8n8.x4.trans.shared.b16 {%0,%1,%2,%3}, [%4];" \
        : "=r"((r)[0]), "=r"((r)[1]), "=r"((r)[2]), "=r"((r)[3]) : "r"(addr))
#define CP_ASYNC16(dst, src) \
    asm volatile("cp.async.cg.shared.global [%0], [%1], 16;" :: "r"(dst), "l"(src))
#define CP_COMMIT() asm volatile("cp.async.commit_group;")
#define CP_WAIT1()  asm volatile("cp.async.wait_group 1;")
#define CP_WAIT0()  asm volatile("cp.async.wait_group 0;")

__device__ __forceinline__ void mma_f16(float* d, const uint32_t* a, const uint32_t* b) {
    asm volatile("mma.sync.aligned.m16n8k16.row.col.f32.f16.f16.f32 "
        "{%0,%1,%2,%3}, {%4,%5,%6,%7}, {%8,%9}, {%0,%1,%2,%3};"
        : "+f"(d[0]), "+f"(d[1]), "+f"(d[2]), "+f"(d[3])
        : "r"(a[0]), "r"(a[1]), "r"(a[2]), "r"(a[3]), "r"(b[0]), "r"(b[1]));
}

__device__ __forceinline__ uint32_t pack_h2(float x, float y) {
    __half2 h = __floats2half2_rn(x, y);
    return *(uint32_t*)&h;
}

// ---------------------------------------------------------------------------
// RoPE table: g_rope[s*32+j] = (cos(s*f_j), sin(s*f_j))
// ---------------------------------------------------------------------------
__global__ void rope_tab_kernel(void) {
    int idx = blockIdx.x * blockDim.x + threadIdx.x;
    if (idx >= SEQL * 32) return;
    int s = idx >> 5, j = idx & 31;
    const float LOGT = 13.122363377404328f;   // ln(500000)
    float f = expf(-(float)j * (LOGT / 32.f));
    float sn, cs;
    sincosf((float)s * f, &sn, &cs);
    g_rope[idx] = make_float2(cs, sn);
}

// ---------------------------------------------------------------------------
// Convert fp32 -> single fp16 (elementwise)
// ---------------------------------------------------------------------------
__global__ void conv_h_kernel(const float* __restrict__ x, __half* __restrict__ y, int n4) {
    int i = blockIdx.x * blockDim.x + threadIdx.x;
    if (i >= n4) return;
    float4 v = ((const float4*)x)[i];
    ((uint2*)y)[i] = make_uint2(pack_h2(v.x, v.y), pack_h2(v.z, v.w));
}

// ---------------------------------------------------------------------------
// Fused 4-matrix transpose to single fp16 (Wq/Wk/Wv -> g_wqkvT, Wo -> g_woT)
// ---------------------------------------------------------------------------
__global__ void tsplit4_kernel(const float* __restrict__ Wq, const float* __restrict__ Wk,
                               const float* __restrict__ Wv, const float* __restrict__ Wo) {
    const float* W;
    int N, roff;
    __half* T;
    if (blockIdx.z == 0)      { W = Wq; N = 2048; roff = 0;    T = g_wqkvT; }
    else if (blockIdx.z == 1) { W = Wk; N = 512;  roff = 2048; T = g_wqkvT; }
    else if (blockIdx.z == 2) { W = Wv; N = 512;  roff = 2560; T = g_wqkvT; }
    else                      { W = Wo; N = 2048; roff = 0;    T = g_woT;   }
    int n0 = blockIdx.x * 32, k0 = blockIdx.y * 32;
    if (n0 >= N) return;

    __shared__ float t[32][33];
    int tx = threadIdx.x, ty = threadIdx.y;
#pragma unroll
    for (int r = 0; r < 4; r++)
        t[ty + 8 * r][tx] = W[(size_t)(k0 + ty + 8 * r) * N + n0 + tx];
    __syncthreads();
#pragma unroll
    for (int r = 0; r < 4; r++) {
        int rr = ty + 8 * r;
        T[(size_t)(roff + n0 + rr) * GK + k0 + tx] = __float2half_rn(t[tx][rr]);
    }
}

// ---------------------------------------------------------------------------
// mma.sync fp16 GEMM: C = A @ B^T, single fp16 operands (1 MMA per k-step).
// 3-stage cp.async ring, 1 barrier/iter, 3 CTAs/SM (single-wave for QKV).
// MODE 0: plain fp32 store. MODE 1: fused RoPE (table) + fp16 pack.
// ---------------------------------------------------------------------------
#define TILE_B   10240
#define STAGE_B  (2 * TILE_B)
#define NSTAGE   3
#define GEMM_SMEM (NSTAGE * STAGE_B)   // 61440

__device__ __forceinline__ void gemm_issue(const __half* const* srcs,
                                           uint32_t sbase, int slot, int k0, int tid) {
#pragma unroll
    for (int t = 0; t < 2; t++) {
        const __half* s = srcs[t] + k0;
        uint32_t dstb = sbase + slot * STAGE_B + t * TILE_B;
#pragma unroll
        for (int c2 = 0; c2 < 2; c2++) {
            int c = c2 * 256 + tid;
            int row = c >> 2, sub = c & 3;
            CP_ASYNC16(dstb + row * 80 + sub * 16, s + (size_t)row * GK + sub * 8);
        }
    }
    CP_COMMIT();
}

template <int MODE>
__global__ __launch_bounds__(256, 3) void gemm_mma(
    const __half* __restrict__ A, const __half* __restrict__ B,
    float* __restrict__ C, int N) {
    extern __shared__ char smem[];
    const uint32_t sbase = smem_u32(smem);
    const int tid = threadIdx.x;
    const int wid = tid >> 5, lane = tid & 31;
    const int wm = wid & 3, wn = wid >> 2;
    const int bm = blockIdx.y, bn = blockIdx.x;

    const __half* srcs[2] = {
        A + (size_t)bm * 128 * GK, B + (size_t)bn * 128 * GK};

    float acc[2][8][4];
#pragma unroll
    for (int i = 0; i < 2; i++)
#pragma unroll
        for (int j = 0; j < 8; j++)
#pragma unroll
            for (int k = 0; k < 4; k++) acc[i][j][k] = 0.f;

    const int NIT = GK / 32;
    gemm_issue(srcs, sbase, 0, 0, tid);
    gemm_issue(srcs, sbase, 1, 32, tid);

    const int a_row = wm * 32 + (lane & 15);
    const int a_koff = (lane >> 4) << 3;
    const int b_row = wn * 64 + (lane & 7) + ((lane >> 4) << 3);
    const int b_koff = ((lane >> 3) & 1) << 3;

    int slot = 0;
    for (int it = 0; it < NIT; it++) {
        if (it + 1 < NIT) { CP_WAIT1(); } else { CP_WAIT0(); }
        __syncthreads();
        if (it + 2 < NIT) {
            int islot = slot + 2; if (islot >= NSTAGE) islot -= NSTAGE;
            gemm_issue(srcs, sbase, islot, (it + 2) * 32, tid);
        }

        uint32_t s_a = sbase + slot * STAGE_B;
        uint32_t s_b = s_a + TILE_B;

#pragma unroll
        for (int ks = 0; ks < 2; ks++) {
            int kc = ks * 16;
            uint32_t ah[2][4];
#pragma unroll
            for (int mf = 0; mf < 2; mf++) {
                uint32_t ro = (a_row + mf * 16) * 80 + (kc + a_koff) * 2;
                LDMX4(ah[mf], s_a + ro);
            }
#pragma unroll
            for (int nh = 0; nh < 2; nh++) {
                uint32_t bb[4][2];
#pragma unroll
                for (int g = 0; g < 2; g++) {
                    uint32_t r[4];
                    uint32_t ro = (b_row + nh * 32 + g * 16) * 80 + (kc + b_koff) * 2;
                    LDMX4(r, s_b + ro);
                    bb[g * 2][0] = r[0]; bb[g * 2][1] = r[1];
                    bb[g * 2 + 1][0] = r[2]; bb[g * 2 + 1][1] = r[3];
                }
#pragma unroll
                for (int mf = 0; mf < 2; mf++)
#pragma unroll
                    for (int nf = 0; nf < 4; nf++)
                        mma_f16(acc[mf][nh * 4 + nf], ah[mf], bb[nf]);
            }
        }
        if (++slot >= NSTAGE) slot = 0;
    }

    const int er = lane >> 2, ec = (lane & 3) * 2;
    if (MODE == 0) {
#pragma unroll
        for (int mf = 0; mf < 2; mf++) {
            float* c0 = C + (size_t)(bm * 128 + wm * 32 + mf * 16 + er) * N + bn * 128 + wn * 64 + ec;
#pragma unroll
            for (int nf = 0; nf < 8; nf++) {
                float* cp = c0 + nf * 8;
                cp[0] = acc[mf][nf][0];
                cp[1] = acc[mf][nf][1];
                cp[8 * (size_t)N + 0] = acc[mf][nf][2];
                cp[8 * (size_t)N + 1] = acc[mf][nf][3];
            }
        }
    } else {
        // fused RoPE (table lookup) + fp16 pack into q/k/v operand arrays
#pragma unroll
        for (int nf = 0; nf < 8; nf++) {
            int n = bn * 128 + wn * 64 + nf * 8 + ec;
            bool dorope = (n < 2560);
            int j0 = n & 31;
#pragma unroll
            for (int mf = 0; mf < 2; mf++) {
#pragma unroll
                for (int rr = 0; rr < 2; rr++) {
                    int row = bm * 128 + wm * 32 + mf * 16 + er + rr * 8;
                    float v0 = acc[mf][nf][rr * 2], v1 = acc[mf][nf][rr * 2 + 1];
                    float y0 = v0, y1 = v1;
                    if (dorope) {
                        float2 cs0 = g_rope[row * 32 + j0];
                        float2 cs1 = g_rope[row * 32 + j0 + 1];
                        y0 = v0 * cs0.x - v1 * cs0.y;
                        y1 = v1 * cs1.x + v0 * cs1.y;
                    }
                    if (n < 2048) {
                        ((uint32_t*)g_q1)[((size_t)row * 2048 + n) >> 1] =
                            pack_h2(y0 * 0.125f, y1 * 0.125f);
                    } else if (n < 2560) {
                        ((uint32_t*)g_k1)[((size_t)row * 512 + (n - 2048)) >> 1] =
                            pack_h2(y0, y1);
                    } else {
                        ((uint32_t*)g_v1)[((size_t)row * 512 + (n - 2560)) >> 1] =
                            pack_h2(y0, y1);
                    }
                }
            }
        }
    }
}

// ---------------------------------------------------------------------------
// Tensor-core flash attention, all-single-fp16, 64 q-rows/CTA, 128 threads.
// S: Q x K (1 MMA). PV: P x V (1 MMA).
// Smem 40KB: Q 8KB + 2 stages of [K 8KB | V 8KB].
// ---------------------------------------------------------------------------
#define AT_STAGE 16384
#define AT_SMEM (8192 + 2 * AT_STAGE)
#define SWZ(row, cb) ((uint32_t)((row) * 128 + ((cb) ^ (((row) & 7) << 4))))

__device__ __forceinline__ void attn_issue_kv(uint32_t base, int jb, int kvh, int tid) {
#pragma unroll
    for (int it = 0; it < 8; it++) {
        const __half* p = (it < 4) ? g_k1 : g_v1;
        int row = (it & 3) * 16 + (tid >> 3);
        int sub = tid & 7;
        size_t off = (size_t)(jb * 64 + row) * 512 + kvh * 64 + sub * 8;
        CP_ASYNC16(base + ((it < 4) ? 0 : 8192) + SWZ(row, sub * 16), p + off);
    }
    CP_COMMIT();
}

__global__ __launch_bounds__(128) void attn_mma(void) {
    extern __shared__ char smem[];
    const uint32_t sb = smem_u32(smem);
    const int tid = threadIdx.x, wid = tid >> 5, lane = tid & 31;
    const int qb = gridDim.x - 1 - blockIdx.x;   // heavy blocks first
    const int h = blockIdx.y, kvh = h >> 2;
    const uint32_t sKV = sb + 8192;

    // issue Q + first KV stage as group 0
#pragma unroll
    for (int it = 0; it < 4; it++) {
        int row = it * 16 + (tid >> 3);
        int sub = tid & 7;
        size_t off = (size_t)(qb * 64 + row) * 2048 + h * 64 + sub * 8;
        CP_ASYNC16(sb + SWZ(row, sub * 16), g_q1 + off);
    }
    attn_issue_kv(sKV, 0, kvh, tid);            // commits group 0 (with Q)
    if (qb >= 1) attn_issue_kv(sKV + AT_STAGE, 1, kvh, tid);  // group 1

    float m0 = -1e30f, m1 = -1e30f, l0 = 0.f, l1 = 0.f;
    float o[8][4];
#pragma unroll
    for (int j = 0; j < 8; j++)
#pragma unroll
        for (int k = 0; k < 4; k++) o[j][k] = 0.f;

    uint32_t qf[4][4];

    const int a_row = wid * 16 + (lane & 15);
    const int a_koff = (lane >> 4) << 3;
    const int b_row0 = (lane & 7) + ((lane >> 4) << 3);
    const int b_koff = ((lane >> 3) & 1) << 3;
    const int v_row0 = lane & 15;
    const int v_coff = (lane >> 4) << 3;

    for (int jb = 0; jb <= qb; jb++) {
        if (jb == 0) {
            if (qb >= 1) { CP_WAIT1(); } else { CP_WAIT0(); }
        } else {
            if (jb + 1 <= qb) {
                attn_issue_kv(sKV + ((jb + 1) & 1) * AT_STAGE, jb + 1, kvh, tid);
                CP_WAIT1();
            } else { CP_WAIT0(); }
        }
        __syncthreads();

        if (jb == 0) {   // Q frags (once)
#pragma unroll
            for (int ks = 0; ks < 4; ks++)
                LDMX4(qf[ks], sb + SWZ(a_row, (ks * 16 + a_koff) * 2));
        }

        const uint32_t st = sKV + (jb & 1) * AT_STAGE;

        // ---- S = Q K^T (1 fp16 MMA; q pre-scaled 0.125) ----
        float s[8][4];
#pragma unroll
        for (int j = 0; j < 8; j++)
#pragma unroll
            for (int k = 0; k < 4; k++) s[j][k] = 0.f;
#pragma unroll
        for (int ks = 0; ks < 4; ks++) {
#pragma unroll
            for (int nb = 0; nb < 4; nb++) {
                uint32_t kb[4];
                uint32_t ro = SWZ(nb * 16 + b_row0, (ks * 16 + b_koff) * 2);
                LDMX4(kb, st + ro);
                mma_f16(s[2 * nb], qf[ks], kb);
                mma_f16(s[2 * nb + 1], qf[ks], kb + 2);
            }
        }

        // ---- causal mask (scale already folded into q) ----
        if (jb == qb) {
            int rp0 = wid * 16 + (lane >> 2);
#pragma unroll
            for (int j = 0; j < 8; j++) {
                int cp = j * 8 + (lane & 3) * 2;
                s[j][0] += (cp > rp0) ? -1e9f : 0.f;
                s[j][1] += (cp + 1 > rp0) ? -1e9f : 0.f;
                s[j][2] += (cp > rp0 + 8) ? -1e9f : 0.f;
                s[j][3] += (cp + 1 > rp0 + 8) ? -1e9f : 0.f;
            }
        }

        // ---- online softmax ----
        float mx0 = -1e30f, mx1 = -1e30f;
#pragma unroll
        for (int j = 0; j < 8; j++) {
            mx0 = fmaxf(mx0, fmaxf(s[j][0], s[j][1]));
            mx1 = fmaxf(mx1, fmaxf(s[j][2], s[j][3]));
        }
        mx0 = fmaxf(mx0, __shfl_xor_sync(0xffffffffu, mx0, 1));
        mx0 = fmaxf(mx0, __shfl_xor_sync(0xffffffffu, mx0, 2));
        mx1 = fmaxf(mx1, __shfl_xor_sync(0xffffffffu, mx1, 1));
        mx1 = fmaxf(mx1, __shfl_xor_sync(0xffffffffu, mx1, 2));
        float nm0 = fmaxf(m0, mx0), nm1 = fmaxf(m1, mx1);
        float al0 = __expf(m0 - nm0), al1 = __expf(m1 - nm1);
        m0 = nm0; m1 = nm1;
        float rs0 = 0.f, rs1 = 0.f;
#pragma unroll
        for (int j = 0; j < 8; j++) {
            s[j][0] = __expf(s[j][0] - nm0);
            s[j][1] = __expf(s[j][1] - nm0);
            s[j][2] = __expf(s[j][2] - nm1);
            s[j][3] = __expf(s[j][3] - nm1);
            rs0 += s[j][0] + s[j][1];
            rs1 += s[j][2] + s[j][3];
        }
        l0 = l0 * al0 + rs0;
        l1 = l1 * al1 + rs1;
#pragma unroll
        for (int j = 0; j < 8; j++) {
            o[j][0] *= al0; o[j][1] *= al0;
            o[j][2] *= al1; o[j][3] *= al1;
        }

        // ---- O += P V (1 fp16 MMA per 8-col block) ----
#pragma unroll
        for (int ks = 0; ks < 4; ks++) {
            uint32_t pa[4];
            pa[0] = pack_h2(s[2 * ks][0], s[2 * ks][1]);
            pa[1] = pack_h2(s[2 * ks][2], s[2 * ks][3]);
            pa[2] = pack_h2(s[2 * ks + 1][0], s[2 * ks + 1][1]);
            pa[3] = pack_h2(s[2 * ks + 1][2], s[2 * ks + 1][3]);
#pragma unroll
            for (int db = 0; db < 4; db++) {
                uint32_t vb[4];
                uint32_t ro = SWZ(ks * 16 + v_row0, (db * 16 + v_coff) * 2);
                LDMX4T(vb, st + 8192 + ro);
                mma_f16(o[2 * db], pa, vb);
                mma_f16(o[2 * db + 1], pa, vb + 2);
            }
        }
        __syncthreads();
    }

    // ---- epilogue: normalize, single fp16 write ----
    l0 += __shfl_xor_sync(0xffffffffu, l0, 1);
    l0 += __shfl_xor_sync(0xffffffffu, l0, 2);
    l1 += __shfl_xor_sync(0xffffffffu, l1, 1);
    l1 += __shfl_xor_sync(0xffffffffu, l1, 2);
    float inv0 = 1.f / l0, inv1 = 1.f / l1;
    int r0 = qb * 64 + wid * 16 + (lane >> 2);
    int cb = h * 64 + (lane & 3) * 2;
#pragma unroll
    for (int j = 0; j < 8; j++) {
        int c = cb + j * 8;
        ((uint32_t*)g_attn)[(r0 * 2048 + c) >> 1] =
            pack_h2(o[j][0] * inv0, o[j][1] * inv0);
        ((uint32_t*)g_attn)[((r0 + 8) * 2048 + c) >> 1] =
            pack_h2(o[j][2] * inv1, o[j][3] * inv1);
    }
}

// ---------------------------------------------------------------------------
extern "C" void kernel_launch(void* const* d_in, const int* in_sizes, int n_in,
                              void* d_out, int out_size) {
    const float* hidden = (const float*)d_in[0];
    const float* Wq = (const float*)d_in[2];
    const float* Wk = (const float*)d_in[3];
    const float* Wv = (const float*)d_in[4];
    const float* Wo = (const float*)d_in[5];
    float* out = (float*)d_out;

    __half *hd, *wq, *wo, *at;
    cudaGetSymbolAddress((void**)&hd, g_hid);
    cudaGetSymbolAddress((void**)&wq, g_wqkvT);
    cudaGetSymbolAddress((void**)&wo, g_woT);
    cudaGetSymbolAddress((void**)&at, g_attn);

    cudaFuncSetAttribute(gemm_mma<0>, cudaFuncAttributeMaxDynamicSharedMemorySize, GEMM_SMEM);
    cudaFuncSetAttribute(gemm_mma<1>, cudaFuncAttributeMaxDynamicSharedMemorySize, GEMM_SMEM);
    cudaFuncSetAttribute(attn_mma, cudaFuncAttributeMaxDynamicSharedMemorySize, AT_SMEM);

    // launch 0: RoPE cos/sin table
    rope_tab_kernel<<<(SEQL * 32 + 255) / 256, 256>>>();
    // launch 1: hidden -> single fp16
    conv_h_kernel<<<(SEQL * HID / 4 + 255) / 256, 256>>>(hidden, hd, SEQL * HID / 4);
    // launch 2: fused Wq/Wk/Wv/Wo transpose to single fp16
    tsplit4_kernel<<<dim3(64, GK / 32, 4), dim3(32, 8)>>>(Wq, Wk, Wv, Wo);
    // launch 3: fused QKV projection + RoPE(table) + fp16 pack (single wave @3 CTAs/SM)
    gemm_mma<1><<<dim3(QKVN / 128, SEQL / 128), 256, GEMM_SMEM>>>(hd, wq, nullptr, QKVN);
    // launch 4: flash attention (all-single fp16)
    attn_mma<<<dim3(SEQL / 64, NH), 128, AT_SMEM>>>();
    // launch 5: O-projection
    gemm_mma<0><<<dim3(HID / 128, SEQL / 128), 256, GEMM_SMEM>>>(at, wo, out, HID);
}